// round 16
// baseline (speedup 1.0000x reference)
#include <cuda_runtime.h>
#include <cuda_bf16.h>
#include <cuda_fp16.h>
#include <cstdint>

#define CC 64
#define KK 20
#define MT 128             // points per pass1 tile
#define NMAX (1 << 20)

// ---------------- device scratch (static; no allocations allowed) -------------
// point-major, 64B (4 x uint4) per point
__device__ uint4  g_h0q[(size_t)NMAX * 4];   // 64 MiB
__device__ double g_acc[5];                  // segnum, segden, l1, cos, cnt
__device__ double g_sum[CC];
__device__ double g_sumsq[CC];
__device__ float2 g_AB[CC];                  // BN-folded affine: h0*A + B
__device__ float4 g_W2p[CC];

// ---------------- helpers -------------------------------------------------------
__device__ __forceinline__ uint32_t smem_u32(const void* p) {
    uint32_t a;
    asm("{ .reg .u64 t; cvta.to.shared.u64 t, %1; cvt.u32.u64 %0, t; }" : "=r"(a) : "l"(p));
    return a;
}
__device__ __forceinline__ unsigned bf2(float hi, float lo) {
    unsigned r;
    asm("cvt.rn.bf16x2.f32 %0, %1, %2;" : "=r"(r) : "f"(hi), "f"(lo));
    return r;
}
__device__ __forceinline__ unsigned short fp8x2(float hi, float lo) {
    unsigned short r;
    asm("cvt.rn.satfinite.e4m3x2.f32 %0, %1, %2;" : "=h"(r) : "f"(hi), "f"(lo));
    return r;
}
__device__ __forceinline__ __half2 fp8_to_h2(unsigned short v) {
    unsigned r;
    asm("cvt.rn.f16x2.e4m3x2 %0, %1;" : "=r"(r) : "h"(v));
    return *reinterpret_cast<__half2*>(&r);
}
__device__ __forceinline__ float wsum(float v) {
#pragma unroll
    for (int o = 16; o > 0; o >>= 1) v += __shfl_down_sync(0xffffffffu, v, o);
    return v;
}
__device__ __forceinline__ void ldsm_x4(uint32_t& a0, uint32_t& a1, uint32_t& a2, uint32_t& a3, uint32_t addr) {
    asm volatile("ldmatrix.sync.aligned.m8n8.x4.shared.b16 {%0,%1,%2,%3}, [%4];"
        : "=r"(a0), "=r"(a1), "=r"(a2), "=r"(a3) : "r"(addr));
}
__device__ __forceinline__ void mma16816(float* d, uint32_t a0, uint32_t a1, uint32_t a2, uint32_t a3,
                                         uint32_t b0, uint32_t b1) {
    asm volatile("mma.sync.aligned.m16n8k16.row.col.f32.bf16.bf16.f32 "
        "{%0,%1,%2,%3}, {%4,%5,%6,%7}, {%8,%9}, {%0,%1,%2,%3};"
        : "+f"(d[0]), "+f"(d[1]), "+f"(d[2]), "+f"(d[3])
        : "r"(a0), "r"(a1), "r"(a2), "r"(a3), "r"(b0), "r"(b1));
}

// ---------------- pass1 smem byte offsets ---------------------------------------
// A: 128 x 144B | B: 88 x 144B | stg: 128 x 36 u32 | bseg | cw
#define SO_A    0
#define SO_B    18432
#define SO_STG  31104
#define SO_BS   49536
#define SO_CW   49616
#define SM1_BYTES 49728

// ---------------- init ----------------------------------------------------------
__global__ void zero_kernel() {
    int t = threadIdx.x;
    if (t < 5) g_acc[t] = 0.0;
    if (t < CC) { g_sum[t] = 0.0; g_sumsq[t] = 0.0; }
}

// prefetch tile t's feat into registers (guarded; zero-fill OOB; streaming loads)
__device__ __forceinline__ void prefetch_tile(const float* __restrict__ feat,
                                              int t, int ntiles, int N, int tid, float4* r) {
    if (t >= ntiles) return;
    const size_t b4 = (size_t)t * MT * (CC / 4);
    const size_t lim = (size_t)N * (CC / 4);
    const float4* src = (const float4*)feat;
#pragma unroll
    for (int it = 0; it < 8; it++) {
        size_t idx = b4 + it * 256 + tid;
        r[it] = (idx < lim) ? __ldcs(src + idx) : make_float4(0.f, 0.f, 0.f, 0.f);
    }
}

// ---------------- pass1: HMMA GEMM + reg-prefetch pipeline ----------------------
__global__ __launch_bounds__(256, 2) void pass1_kernel(
    const float* __restrict__ feat, const int* __restrict__ segment,
    const float* __restrict__ W1, const float* __restrict__ Wseg,
    const float* __restrict__ bseg, const float* __restrict__ cw,
    int N, int ntiles)
{
    extern __shared__ char sm[];
    const uint32_t smb = smem_u32(sm);
    unsigned* stg = (unsigned*)(sm + SO_STG);
    float* bsf = (float*)(sm + SO_BS);
    float* cwf = (float*)(sm + SO_CW);
    const int tid = threadIdx.x;
    const int w = tid >> 5, lane = tid & 31;
    const int gid = lane >> 2, tig = lane & 3;

    // B = [W1 | Wseg | 0]: rows n (out ch), cols k; bf16, pitch 144B
    for (int i = tid; i < 88 * CC; i += 256) {
        int n = i >> 6, k = i & 63;
        float v = (n < 64) ? W1[k * 64 + n] : ((n < 84) ? Wseg[k * 20 + (n - 64)] : 0.f);
        *(__nv_bfloat16*)(sm + SO_B + n * 144 + 2 * k) = __float2bfloat16(v);
    }
    if (tid < KK) { bsf[tid] = bseg[tid]; cwf[tid] = cw[tid]; }
    __syncthreads();

    const uint32_t aAddrBase = smb + SO_A + (16 * w + (lane & 15)) * 144 + 16 * (lane >> 4);
    const uint32_t bAddrBase = smb + SO_B + gid * 144 + tig * 4;

    float segnum = 0.f, segden = 0.f;
    float s0 = 0.f, s1 = 0.f, q0 = 0.f, q1 = 0.f;

    float4 pf[8];
    prefetch_tile(feat, blockIdx.x, ntiles, N, tid, pf);

    for (int t = blockIdx.x; t < ntiles; t += gridDim.x) {
        const int base = t * MT;

        // ---- STS prefetched A tile (f32 regs -> bf16 smem, pitch 144B) ----
#pragma unroll
        for (int it = 0; it < 8; it++) {
            int l4 = it * 256 + tid;
            float4 v = pf[it];
            int pt = l4 >> 4, c4 = (l4 & 15) * 4;
            *(uint2*)(sm + SO_A + pt * 144 + c4 * 2) =
                make_uint2(bf2(v.y, v.x), bf2(v.w, v.z));
        }
        // ---- issue next tile's DRAM loads BEFORE the barrier (max overlap) ----
        prefetch_tile(feat, t + gridDim.x, ntiles, N, tid, pf);
        __syncthreads();

        // ---- GEMM: D[128 x 88] = A @ B^T via m16n8k16, warp owns 16 rows ----
        float acc[11][4];
#pragma unroll
        for (int j = 0; j < 11; j++) {
            acc[j][0] = 0.f; acc[j][1] = 0.f; acc[j][2] = 0.f; acc[j][3] = 0.f;
        }
#pragma unroll
        for (int s = 0; s < 4; s++) {
            uint32_t a0, a1, a2, a3;
            ldsm_x4(a0, a1, a2, a3, aAddrBase + 32 * s);
            uint32_t bA = bAddrBase + 32 * s;
#pragma unroll
            for (int j = 0; j < 11; j++) {
                uint32_t b0, b1;
                asm volatile("ld.shared.b32 %0, [%1];" : "=r"(b0) : "r"(bA + j * 1152));
                asm volatile("ld.shared.b32 %0, [%1];" : "=r"(b1) : "r"(bA + j * 1152 + 16));
                mma16816(acc[j], a0, a1, a2, a3, b0, b1);
            }
        }

        // ---- CE directly from accumulators (quad shuffles), rows r0 and r0+8 ----
        {
            const int r0 = 16 * w + gid;
#pragma unroll
            for (int half = 0; half < 2; half++) {
                const int row = r0 + 8 * half;
                const int p = base + row;
                float m = -1e30f;
                float lv[6];
#pragma unroll
                for (int j = 0; j < 3; j++) {
#pragma unroll
                    for (int k = 0; k < 2; k++) {
                        int L = 8 * j + 2 * tig + k;
                        float v = (L < KK) ? (acc[8 + j][2 * half + k] + bsf[L]) : -1e30f;
                        lv[2 * j + k] = v;
                        m = fmaxf(m, v);
                    }
                }
                m = fmaxf(m, __shfl_xor_sync(0xffffffffu, m, 1));
                m = fmaxf(m, __shfl_xor_sync(0xffffffffu, m, 2));
                float s = 0.f;
#pragma unroll
                for (int i = 0; i < 6; i++) {
                    int L = 8 * (i >> 1) + 2 * tig + (i & 1);
                    if (L < KK) s += __expf(lv[i] - m);
                }
                s += __shfl_xor_sync(0xffffffffu, s, 1);
                s += __shfl_xor_sync(0xffffffffu, s, 2);
                float lse = m + __logf(s);
                bool inr = (p < N);
                int sg = inr ? segment[p] : -1;
                bool valid = inr && (sg != -1);
                int tgt = valid ? sg : 0;
                float lt = 0.f;
#pragma unroll
                for (int i = 0; i < 6; i++) {
                    int L = 8 * (i >> 1) + 2 * tig + (i & 1);
                    if (L < KK && L == tgt) lt += lv[i];
                }
                lt += __shfl_xor_sync(0xffffffffu, lt, 1);
                lt += __shfl_xor_sync(0xffffffffu, lt, 2);
                if (tig == 0) {
                    float wt = valid ? cwf[tgt] : 0.f;
                    segnum += wt * (lse - lt);
                    segden += wt;
                }
            }
        }

        // ---- stage h (cols 0..63) as bf16x2 ----
        {
            int r0 = 16 * w + gid;
#pragma unroll
            for (int j = 0; j < 8; j++) {
                stg[r0 * 36 + 4 * j + tig]       = bf2(acc[j][1], acc[j][0]);
                stg[(r0 + 8) * 36 + 4 * j + tig] = bf2(acc[j][3], acc[j][2]);
            }
        }
        __syncthreads();

        // ---- fp8 h0 store (point-major layout, coalesced, streaming) ----
#pragma unroll
        for (int it = 0; it < 2; it++) {
            int idx = it * 256 + tid;
            int pt = idx >> 2, c16 = idx & 3;
            if (base + pt < N) {
                unsigned r[4];
#pragma unroll
                for (int z = 0; z < 4; z++) {
                    unsigned u0 = stg[pt * 36 + c16 * 8 + 2 * z];
                    unsigned u1 = stg[pt * 36 + c16 * 8 + 2 * z + 1];
                    float2 f0 = __bfloat1622float2(*(__nv_bfloat162*)&u0);
                    float2 f1 = __bfloat1622float2(*(__nv_bfloat162*)&u1);
                    unsigned short e0 = fp8x2(f0.y, f0.x);
                    unsigned short e1 = fp8x2(f1.y, f1.x);
                    r[z] = (unsigned)e0 | ((unsigned)e1 << 16);
                }
                __stcs(&g_h0q[(size_t)(base + pt) * 4 + c16], make_uint4(r[0], r[1], r[2], r[3]));
            }
        }

        // ---- BN stats (channel-major scan of stage) ----
        // no trailing barrier: next stage writes are behind the next post-A sync
        {
            int j = lane, g8 = w;
#pragma unroll
            for (int q = 0; q < 16; q++) {
                int pt = g8 * 16 + q;
                if (base + pt < N) {
                    unsigned u = stg[pt * 36 + j];
                    float2 hh = __bfloat1622float2(*(__nv_bfloat162*)&u);
                    s0 += hh.x; s1 += hh.y;
                    q0 = fmaf(hh.x, hh.x, q0);
                    q1 = fmaf(hh.y, hh.y, q1);
                }
            }
        }
    }

    // ---- reductions -> double atomics ----
    __syncthreads();
    float sn = wsum(segnum), sd = wsum(segden);
    float* red = (float*)stg;
    if (lane == 0) { red[1024 + w] = sn; red[1040 + w] = sd; }
    red[tid] = s0; red[256 + tid] = s1; red[512 + tid] = q0; red[768 + tid] = q1;
    __syncthreads();
    if (tid == 0) {
        float a = 0.f, b = 0.f;
        for (int i = 0; i < 8; i++) { a += red[1024 + i]; b += red[1040 + i]; }
        atomicAdd(&g_acc[0], (double)a);
        atomicAdd(&g_acc[1], (double)b);
    }
    if (tid < 32) {
        float a0 = 0.f, a1 = 0.f, b0 = 0.f, b1 = 0.f;
        for (int g = 0; g < 8; g++) {
            a0 += red[g * 32 + tid];
            a1 += red[256 + g * 32 + tid];
            b0 += red[512 + g * 32 + tid];
            b1 += red[768 + g * 32 + tid];
        }
        atomicAdd(&g_sum[2 * tid],       (double)a0);
        atomicAdd(&g_sum[2 * tid + 1],   (double)a1);
        atomicAdd(&g_sumsq[2 * tid],     (double)b0);
        atomicAdd(&g_sumsq[2 * tid + 1], (double)b1);
    }
}

// ---------------- finalize BN affine (b1 cancels through BN) -------------------
__global__ void finalize_kernel(const float* __restrict__ gamma,
                                const float* __restrict__ beta,
                                const float* __restrict__ W2, int N)
{
    int ch = threadIdx.x;
    if (ch < CC) {
        double inv_n = 1.0 / (double)N;
        double m0  = g_sum[ch] * inv_n;
        double var = g_sumsq[ch] * inv_n - m0 * m0;
        float inv = rsqrtf((float)var + 1e-3f);
        float A = gamma[ch] * inv;
        float B = beta[ch] - (float)m0 * A;
        g_AB[ch]  = make_float2(A, B);
        g_W2p[ch] = make_float4(W2[3 * ch], W2[3 * ch + 1], W2[3 * ch + 2], 0.f);
    }
}

// ---------------- pass3: 2 points/thread, AB/W2 loads amortized -----------------
__global__ __launch_bounds__(256, 3) void pass3_kernel(
    const float* __restrict__ coord, const int* __restrict__ instance,
    const float* __restrict__ cent, const float* __restrict__ b2,
    int N, int nt3)
{
    __shared__ unsigned stg[512 * 17];   // 512 points per tile
    __shared__ float2 ABs[CC];
    __shared__ float4 W2s[CC];
    __shared__ float rb[24];
    const int tid = threadIdx.x;
    if (tid < CC) { ABs[tid] = g_AB[tid]; W2s[tid] = g_W2p[tid]; }
    const float b20 = b2[0], b21 = b2[1], b22 = b2[2];
    __syncthreads();

    float aL1 = 0.f, aCos = 0.f, aCnt = 0.f;

    for (int t = blockIdx.x; t < nt3; t += gridDim.x) {
        const int base = t * 512;
#pragma unroll
        for (int it = 0; it < 8; it++) {
            int idx = it * 256 + tid;
            int pt = idx >> 2, c16 = idx & 3;
            uint4 v = make_uint4(0, 0, 0, 0);
            if (base + pt < N) v = __ldcs(&g_h0q[(size_t)(base + pt) * 4 + c16]);
            unsigned* d = stg + pt * 17 + c16 * 4;   // pitch 17: scalar stores
            d[0] = v.x; d[1] = v.y; d[2] = v.z; d[3] = v.w;
        }
        __syncthreads();

        const int pA = base + tid;
        const int pB = base + 256 + tid;
        float a0 = b20, a1 = b21, a2 = b22;
        float c0 = b20, c1 = b21, c2 = b22;
#pragma unroll
        for (int j = 0; j < 16; j++) {
            unsigned uA = stg[tid * 17 + j];
            unsigned uB = stg[(tid + 256) * 17 + j];
            float2 fA01 = __half22float2(fp8_to_h2((unsigned short)(uA & 0xffffu)));
            float2 fA23 = __half22float2(fp8_to_h2((unsigned short)(uA >> 16)));
            float2 fB01 = __half22float2(fp8_to_h2((unsigned short)(uB & 0xffffu)));
            float2 fB23 = __half22float2(fp8_to_h2((unsigned short)(uB >> 16)));
            float hvA[4] = {fA01.x, fA01.y, fA23.x, fA23.y};
            float hvB[4] = {fB01.x, fB01.y, fB23.x, fB23.y};
            int c = 4 * j;
#pragma unroll
            for (int z = 0; z < 4; z++) {
                float2 ab = ABs[c + z];
                float4 ww = W2s[c + z];
                float vA = fmaxf(fmaf(hvA[z], ab.x, ab.y), 0.f);
                float vB = fmaxf(fmaf(hvB[z], ab.x, ab.y), 0.f);
                a0 = fmaf(vA, ww.x, a0); a1 = fmaf(vA, ww.y, a1); a2 = fmaf(vA, ww.z, a2);
                c0 = fmaf(vB, ww.x, c0); c1 = fmaf(vB, ww.y, c1); c2 = fmaf(vB, ww.z, c2);
            }
        }
        if (pA < N) {
            int inst = instance[pA];
            if (inst != -1) {
                float g0 = __ldcs(cent + 3 * pA)     - __ldcs(coord + 3 * pA);
                float g1 = __ldcs(cent + 3 * pA + 1) - __ldcs(coord + 3 * pA + 1);
                float g2 = __ldcs(cent + 3 * pA + 2) - __ldcs(coord + 3 * pA + 2);
                aL1 += fabsf(a0 - g0) + fabsf(a1 - g1) + fabsf(a2 - g2);
                float np = sqrtf(a0 * a0 + a1 * a1 + a2 * a2);
                float ng = sqrtf(g0 * g0 + g1 * g1 + g2 * g2);
                float dt = a0 * g0 + a1 * g1 + a2 * g2;
                aCos += -dt / ((np + 1e-8f) * (ng + 1e-8f));
                aCnt += 1.f;
            }
        }
        if (pB < N) {
            int inst = instance[pB];
            if (inst != -1) {
                float g0 = __ldcs(cent + 3 * pB)     - __ldcs(coord + 3 * pB);
                float g1 = __ldcs(cent + 3 * pB + 1) - __ldcs(coord + 3 * pB + 1);
                float g2 = __ldcs(cent + 3 * pB + 2) - __ldcs(coord + 3 * pB + 2);
                aL1 += fabsf(c0 - g0) + fabsf(c1 - g1) + fabsf(c2 - g2);
                float np = sqrtf(c0 * c0 + c1 * c1 + c2 * c2);
                float ng = sqrtf(g0 * g0 + g1 * g1 + g2 * g2);
                float dt = c0 * g0 + c1 * g1 + c2 * g2;
                aCos += -dt / ((np + 1e-8f) * (ng + 1e-8f));
                aCnt += 1.f;
            }
        }
        __syncthreads();
    }

    float a = wsum(aL1), b = wsum(aCos), c = wsum(aCnt);
    int wid = tid >> 5, lid = tid & 31;
    if (lid == 0) { rb[wid] = a; rb[8 + wid] = b; rb[16 + wid] = c; }
    __syncthreads();
    if (tid == 0) {
        float x = 0.f, y = 0.f, z = 0.f;
        for (int i = 0; i < 8; i++) { x += rb[i]; y += rb[8 + i]; z += rb[16 + i]; }
        atomicAdd(&g_acc[2], (double)x);
        atomicAdd(&g_acc[3], (double)y);
        atomicAdd(&g_acc[4], (double)z);
    }
}

// ---------------- final combine -------------------------------------------------
__global__ void out_kernel(float* __restrict__ out) {
    double seg   = g_acc[0] / g_acc[1];
    double denom = g_acc[4] + 1e-8;
    double l1    = g_acc[2] / denom;
    double cs    = g_acc[3] / denom;
    out[0] = (float)(seg + l1 + cs);
    out[1] = (float)seg;
    out[2] = (float)l1;
    out[3] = (float)cs;
}

// ---------------- launch ---------------------------------------------------------
extern "C" void kernel_launch(void* const* d_in, const int* in_sizes, int n_in,
                              void* d_out, int out_size)
{
    const float* feat     = (const float*)d_in[0];
    const float* coord    = (const float*)d_in[1];
    const int*   segment  = (const int*)d_in[2];
    const int*   instance = (const int*)d_in[3];
    const float* cent     = (const float*)d_in[4];
    const float* W1       = (const float*)d_in[5];
    // d_in[6] = b1 (cancels through BN)
    const float* gamma    = (const float*)d_in[7];
    const float* beta     = (const float*)d_in[8];
    const float* W2       = (const float*)d_in[9];
    const float* b2       = (const float*)d_in[10];
    const float* Wseg     = (const float*)d_in[11];
    const float* bseg     = (const float*)d_in[12];
    const float* cw       = (const float*)d_in[13];

    int N = in_sizes[0] / CC;
    if (N > NMAX) N = NMAX;
    int ntiles = (N + MT - 1) / MT;
    int nt3    = (N + 511) / 512;
    int grid1 = ntiles < 296 ? ntiles : 296;
    int grid3 = nt3 < 444 ? nt3 : 444;

    cudaFuncSetAttribute(pass1_kernel, cudaFuncAttributeMaxDynamicSharedMemorySize, SM1_BYTES);

    zero_kernel<<<1, 64>>>();
    pass1_kernel<<<grid1, 256, SM1_BYTES>>>(feat, segment, W1, Wseg, bseg, cw, N, ntiles);
    finalize_kernel<<<1, 64>>>(gamma, beta, W2, N);
    pass3_kernel<<<grid3, 256>>>(coord, instance, cent, b2, N, nt3);
    out_kernel<<<1, 1>>>((float*)d_out);
}

// round 17
// speedup vs baseline: 1.4747x; 1.4747x over previous
#include <cuda_runtime.h>
#include <cuda_bf16.h>
#include <cuda_fp16.h>
#include <cstdint>

#define CC 64
#define KK 20
#define MT 128             // points per pass1 tile
#define NMAX (1 << 20)

// ---------------- device scratch (static; no allocations allowed) -------------
// point-major, 64B (4 x uint4) per point
__device__ uint4  g_h0q[(size_t)NMAX * 4];   // 64 MiB
__device__ double g_acc[5];                  // segnum, segden, l1, cos, cnt
__device__ double g_sum[CC];
__device__ double g_sumsq[CC];
__device__ int    g_done;

// ---------------- helpers -------------------------------------------------------
__device__ __forceinline__ uint32_t smem_u32(const void* p) {
    uint32_t a;
    asm("{ .reg .u64 t; cvta.to.shared.u64 t, %1; cvt.u32.u64 %0, t; }" : "=r"(a) : "l"(p));
    return a;
}
__device__ __forceinline__ unsigned bf2(float hi, float lo) {
    unsigned r;
    asm("cvt.rn.bf16x2.f32 %0, %1, %2;" : "=r"(r) : "f"(hi), "f"(lo));
    return r;
}
__device__ __forceinline__ unsigned short fp8x2(float hi, float lo) {
    unsigned short r;
    asm("cvt.rn.satfinite.e4m3x2.f32 %0, %1, %2;" : "=h"(r) : "f"(hi), "f"(lo));
    return r;
}
__device__ __forceinline__ __half2 fp8_to_h2(unsigned short v) {
    unsigned r;
    asm("cvt.rn.f16x2.e4m3x2 %0, %1;" : "=r"(r) : "h"(v));
    return *reinterpret_cast<__half2*>(&r);
}
__device__ __forceinline__ float wsum(float v) {
#pragma unroll
    for (int o = 16; o > 0; o >>= 1) v += __shfl_down_sync(0xffffffffu, v, o);
    return v;
}
__device__ __forceinline__ void ldsm_x4(uint32_t& a0, uint32_t& a1, uint32_t& a2, uint32_t& a3, uint32_t addr) {
    asm volatile("ldmatrix.sync.aligned.m8n8.x4.shared.b16 {%0,%1,%2,%3}, [%4];"
        : "=r"(a0), "=r"(a1), "=r"(a2), "=r"(a3) : "r"(addr));
}
__device__ __forceinline__ void mma16816(float* d, uint32_t a0, uint32_t a1, uint32_t a2, uint32_t a3,
                                         uint32_t b0, uint32_t b1) {
    asm volatile("mma.sync.aligned.m16n8k16.row.col.f32.bf16.bf16.f32 "
        "{%0,%1,%2,%3}, {%4,%5,%6,%7}, {%8,%9}, {%0,%1,%2,%3};"
        : "+f"(d[0]), "+f"(d[1]), "+f"(d[2]), "+f"(d[3])
        : "r"(a0), "r"(a1), "r"(a2), "r"(a3), "r"(b0), "r"(b1));
}

// ---------------- pass1 smem byte offsets ---------------------------------------
// A: 128 x 144B | B: 88 x 144B | stg: 128 x 36 u32 | bseg | cw
#define SO_A    0
#define SO_B    18432
#define SO_STG  31104
#define SO_BS   49536
#define SO_CW   49616
#define SM1_BYTES 49728

// ---------------- init ----------------------------------------------------------
__global__ void zero_kernel() {
    int t = threadIdx.x;
    if (t < 5) g_acc[t] = 0.0;
    if (t < CC) { g_sum[t] = 0.0; g_sumsq[t] = 0.0; }
    if (t == 0) g_done = 0;
}

// prefetch tile t's feat into registers (guarded; zero-fill OOB)
__device__ __forceinline__ void prefetch_tile(const float* __restrict__ feat,
                                              int t, int ntiles, int N, int tid, float4* r) {
    if (t >= ntiles) return;
    const size_t b4 = (size_t)t * MT * (CC / 4);
    const size_t lim = (size_t)N * (CC / 4);
    const float4* src = (const float4*)feat;
#pragma unroll
    for (int it = 0; it < 8; it++) {
        size_t idx = b4 + it * 256 + tid;
        r[it] = (idx < lim) ? src[idx] : make_float4(0.f, 0.f, 0.f, 0.f);
    }
}

// ---------------- pass1: HMMA GEMM + reg-prefetch pipeline ----------------------
__global__ __launch_bounds__(256, 2) void pass1_kernel(
    const float* __restrict__ feat, const int* __restrict__ segment,
    const float* __restrict__ W1, const float* __restrict__ Wseg,
    const float* __restrict__ bseg, const float* __restrict__ cw,
    int N, int ntiles)
{
    extern __shared__ char sm[];
    const uint32_t smb = smem_u32(sm);
    unsigned* stg = (unsigned*)(sm + SO_STG);
    float* bsf = (float*)(sm + SO_BS);
    float* cwf = (float*)(sm + SO_CW);
    const int tid = threadIdx.x;
    const int w = tid >> 5, lane = tid & 31;
    const int gid = lane >> 2, tig = lane & 3;

    // B = [W1 | Wseg | 0]: rows n (out ch), cols k; bf16, pitch 144B
    for (int i = tid; i < 88 * CC; i += 256) {
        int n = i >> 6, k = i & 63;
        float v = (n < 64) ? W1[k * 64 + n] : ((n < 84) ? Wseg[k * 20 + (n - 64)] : 0.f);
        *(__nv_bfloat16*)(sm + SO_B + n * 144 + 2 * k) = __float2bfloat16(v);
    }
    if (tid < KK) { bsf[tid] = bseg[tid]; cwf[tid] = cw[tid]; }
    __syncthreads();

    const uint32_t aAddrBase = smb + SO_A + (16 * w + (lane & 15)) * 144 + 16 * (lane >> 4);
    const uint32_t bAddrBase = smb + SO_B + gid * 144 + tig * 4;

    float segnum = 0.f, segden = 0.f;
    float s0 = 0.f, s1 = 0.f, q0 = 0.f, q1 = 0.f;

    float4 pf[8];
    prefetch_tile(feat, blockIdx.x, ntiles, N, tid, pf);

    for (int t = blockIdx.x; t < ntiles; t += gridDim.x) {
        const int base = t * MT;

        // ---- STS prefetched A tile (f32 regs -> bf16 smem, pitch 144B) ----
#pragma unroll
        for (int it = 0; it < 8; it++) {
            int l4 = it * 256 + tid;
            float4 v = pf[it];
            int pt = l4 >> 4, c4 = (l4 & 15) * 4;
            *(uint2*)(sm + SO_A + pt * 144 + c4 * 2) =
                make_uint2(bf2(v.y, v.x), bf2(v.w, v.z));
        }
        // ---- issue next tile's DRAM loads BEFORE the barrier (max overlap) ----
        prefetch_tile(feat, t + gridDim.x, ntiles, N, tid, pf);
        __syncthreads();

        // ---- GEMM: D[128 x 88] = A @ B^T via m16n8k16, warp owns 16 rows ----
        float acc[11][4];
#pragma unroll
        for (int j = 0; j < 11; j++) {
            acc[j][0] = 0.f; acc[j][1] = 0.f; acc[j][2] = 0.f; acc[j][3] = 0.f;
        }
#pragma unroll
        for (int s = 0; s < 4; s++) {
            uint32_t a0, a1, a2, a3;
            ldsm_x4(a0, a1, a2, a3, aAddrBase + 32 * s);
            uint32_t bA = bAddrBase + 32 * s;
#pragma unroll
            for (int j = 0; j < 11; j++) {
                uint32_t b0, b1;
                asm volatile("ld.shared.b32 %0, [%1];" : "=r"(b0) : "r"(bA + j * 1152));
                asm volatile("ld.shared.b32 %0, [%1];" : "=r"(b1) : "r"(bA + j * 1152 + 16));
                mma16816(acc[j], a0, a1, a2, a3, b0, b1);
            }
        }

        // ---- CE directly from accumulators (quad shuffles), rows r0 and r0+8 ----
        {
            const int r0 = 16 * w + gid;
#pragma unroll
            for (int half = 0; half < 2; half++) {
                const int row = r0 + 8 * half;
                const int p = base + row;
                float m = -1e30f;
                float lv[6];
#pragma unroll
                for (int j = 0; j < 3; j++) {
#pragma unroll
                    for (int k = 0; k < 2; k++) {
                        int L = 8 * j + 2 * tig + k;
                        float v = (L < KK) ? (acc[8 + j][2 * half + k] + bsf[L]) : -1e30f;
                        lv[2 * j + k] = v;
                        m = fmaxf(m, v);
                    }
                }
                m = fmaxf(m, __shfl_xor_sync(0xffffffffu, m, 1));
                m = fmaxf(m, __shfl_xor_sync(0xffffffffu, m, 2));
                float s = 0.f;
#pragma unroll
                for (int i = 0; i < 6; i++) {
                    int L = 8 * (i >> 1) + 2 * tig + (i & 1);
                    if (L < KK) s += __expf(lv[i] - m);
                }
                s += __shfl_xor_sync(0xffffffffu, s, 1);
                s += __shfl_xor_sync(0xffffffffu, s, 2);
                float lse = m + __logf(s);
                bool inr = (p < N);
                int sg = inr ? segment[p] : -1;
                bool valid = inr && (sg != -1);
                int tgt = valid ? sg : 0;
                float lt = 0.f;
#pragma unroll
                for (int i = 0; i < 6; i++) {
                    int L = 8 * (i >> 1) + 2 * tig + (i & 1);
                    if (L < KK && L == tgt) lt += lv[i];
                }
                lt += __shfl_xor_sync(0xffffffffu, lt, 1);
                lt += __shfl_xor_sync(0xffffffffu, lt, 2);
                if (tig == 0) {
                    float wt = valid ? cwf[tgt] : 0.f;
                    segnum += wt * (lse - lt);
                    segden += wt;
                }
            }
        }

        // ---- stage h (cols 0..63) as bf16x2 ----
        {
            int r0 = 16 * w + gid;
#pragma unroll
            for (int j = 0; j < 8; j++) {
                stg[r0 * 36 + 4 * j + tig]       = bf2(acc[j][1], acc[j][0]);
                stg[(r0 + 8) * 36 + 4 * j + tig] = bf2(acc[j][3], acc[j][2]);
            }
        }
        __syncthreads();

        // ---- fp8 h0 store (point-major layout, coalesced) ----
#pragma unroll
        for (int it = 0; it < 2; it++) {
            int idx = it * 256 + tid;
            int pt = idx >> 2, c16 = idx & 3;
            if (base + pt < N) {
                unsigned r[4];
#pragma unroll
                for (int z = 0; z < 4; z++) {
                    unsigned u0 = stg[pt * 36 + c16 * 8 + 2 * z];
                    unsigned u1 = stg[pt * 36 + c16 * 8 + 2 * z + 1];
                    float2 f0 = __bfloat1622float2(*(__nv_bfloat162*)&u0);
                    float2 f1 = __bfloat1622float2(*(__nv_bfloat162*)&u1);
                    unsigned short e0 = fp8x2(f0.y, f0.x);
                    unsigned short e1 = fp8x2(f1.y, f1.x);
                    r[z] = (unsigned)e0 | ((unsigned)e1 << 16);
                }
                g_h0q[(size_t)(base + pt) * 4 + c16] = make_uint4(r[0], r[1], r[2], r[3]);
            }
        }

        // ---- BN stats (channel-major scan of stage) ----
        // no trailing barrier: next stage writes are behind the next post-A sync
        {
            int j = lane, g8 = w;
#pragma unroll
            for (int q = 0; q < 16; q++) {
                int pt = g8 * 16 + q;
                if (base + pt < N) {
                    unsigned u = stg[pt * 36 + j];
                    float2 hh = __bfloat1622float2(*(__nv_bfloat162*)&u);
                    s0 += hh.x; s1 += hh.y;
                    q0 = fmaf(hh.x, hh.x, q0);
                    q1 = fmaf(hh.y, hh.y, q1);
                }
            }
        }
    }

    // ---- reductions -> double atomics ----
    __syncthreads();
    float sn = wsum(segnum), sd = wsum(segden);
    float* red = (float*)stg;
    if (lane == 0) { red[1024 + w] = sn; red[1040 + w] = sd; }
    red[tid] = s0; red[256 + tid] = s1; red[512 + tid] = q0; red[768 + tid] = q1;
    __syncthreads();
    if (tid == 0) {
        float a = 0.f, b = 0.f;
        for (int i = 0; i < 8; i++) { a += red[1024 + i]; b += red[1040 + i]; }
        atomicAdd(&g_acc[0], (double)a);
        atomicAdd(&g_acc[1], (double)b);
    }
    if (tid < 32) {
        float a0 = 0.f, a1 = 0.f, b0 = 0.f, b1 = 0.f;
        for (int g = 0; g < 8; g++) {
            a0 += red[g * 32 + tid];
            a1 += red[256 + g * 32 + tid];
            b0 += red[512 + g * 32 + tid];
            b1 += red[768 + g * 32 + tid];
        }
        atomicAdd(&g_sum[2 * tid],       (double)a0);
        atomicAdd(&g_sum[2 * tid + 1],   (double)a1);
        atomicAdd(&g_sumsq[2 * tid],     (double)b0);
        atomicAdd(&g_sumsq[2 * tid + 1], (double)b1);
    }
}

// ---------------- pass3: finalize + bias head + losses + last-block out --------
__global__ __launch_bounds__(256, 3) void pass3_kernel(
    const float* __restrict__ coord, const int* __restrict__ instance,
    const float* __restrict__ cent, const float* __restrict__ b2,
    const float* __restrict__ gamma, const float* __restrict__ beta,
    const float* __restrict__ W2, float* __restrict__ out,
    int N, int nt3)
{
    __shared__ unsigned stg[512 * 17];   // 512 points per tile
    __shared__ float2 ABs[CC];
    __shared__ float4 W2s[CC];
    __shared__ float rb[24];
    const int tid = threadIdx.x;

    // ---- inline finalize: BN affine from global stats (b1 cancels thru BN) ----
    if (tid < CC) {
        double inv_n = 1.0 / (double)N;
        double m0  = g_sum[tid] * inv_n;
        double var = g_sumsq[tid] * inv_n - m0 * m0;
        float inv = rsqrtf((float)var + 1e-3f);
        float A = gamma[tid] * inv;
        float B = beta[tid] - (float)m0 * A;
        ABs[tid] = make_float2(A, B);
        W2s[tid] = make_float4(W2[3 * tid], W2[3 * tid + 1], W2[3 * tid + 2], 0.f);
    }
    const float b20 = b2[0], b21 = b2[1], b22 = b2[2];
    __syncthreads();

    float aL1 = 0.f, aCos = 0.f, aCnt = 0.f;

    for (int t = blockIdx.x; t < nt3; t += gridDim.x) {
        const int base = t * 512;
#pragma unroll
        for (int it = 0; it < 8; it++) {
            int idx = it * 256 + tid;
            int pt = idx >> 2, c16 = idx & 3;
            uint4 v = make_uint4(0, 0, 0, 0);
            if (base + pt < N) v = g_h0q[(size_t)(base + pt) * 4 + c16];
            unsigned* d = stg + pt * 17 + c16 * 4;   // pitch 17: scalar stores
            d[0] = v.x; d[1] = v.y; d[2] = v.z; d[3] = v.w;
        }
        __syncthreads();

        const int pA = base + tid;
        const int pB = base + 256 + tid;
        float a0 = b20, a1 = b21, a2 = b22;
        float c0 = b20, c1 = b21, c2 = b22;
#pragma unroll
        for (int j = 0; j < 16; j++) {
            unsigned uA = stg[tid * 17 + j];
            unsigned uB = stg[(tid + 256) * 17 + j];
            float2 fA01 = __half22float2(fp8_to_h2((unsigned short)(uA & 0xffffu)));
            float2 fA23 = __half22float2(fp8_to_h2((unsigned short)(uA >> 16)));
            float2 fB01 = __half22float2(fp8_to_h2((unsigned short)(uB & 0xffffu)));
            float2 fB23 = __half22float2(fp8_to_h2((unsigned short)(uB >> 16)));
            float hvA[4] = {fA01.x, fA01.y, fA23.x, fA23.y};
            float hvB[4] = {fB01.x, fB01.y, fB23.x, fB23.y};
            int c = 4 * j;
#pragma unroll
            for (int z = 0; z < 4; z++) {
                float2 ab = ABs[c + z];
                float4 ww = W2s[c + z];
                float vA = fmaxf(fmaf(hvA[z], ab.x, ab.y), 0.f);
                float vB = fmaxf(fmaf(hvB[z], ab.x, ab.y), 0.f);
                a0 = fmaf(vA, ww.x, a0); a1 = fmaf(vA, ww.y, a1); a2 = fmaf(vA, ww.z, a2);
                c0 = fmaf(vB, ww.x, c0); c1 = fmaf(vB, ww.y, c1); c2 = fmaf(vB, ww.z, c2);
            }
        }
        if (pA < N) {
            int inst = instance[pA];
            if (inst != -1) {
                float g0 = cent[3 * pA]     - coord[3 * pA];
                float g1 = cent[3 * pA + 1] - coord[3 * pA + 1];
                float g2 = cent[3 * pA + 2] - coord[3 * pA + 2];
                aL1 += fabsf(a0 - g0) + fabsf(a1 - g1) + fabsf(a2 - g2);
                float np = sqrtf(a0 * a0 + a1 * a1 + a2 * a2);
                float ng = sqrtf(g0 * g0 + g1 * g1 + g2 * g2);
                float dt = a0 * g0 + a1 * g1 + a2 * g2;
                aCos += -dt / ((np + 1e-8f) * (ng + 1e-8f));
                aCnt += 1.f;
            }
        }
        if (pB < N) {
            int inst = instance[pB];
            if (inst != -1) {
                float g0 = cent[3 * pB]     - coord[3 * pB];
                float g1 = cent[3 * pB + 1] - coord[3 * pB + 1];
                float g2 = cent[3 * pB + 2] - coord[3 * pB + 2];
                aL1 += fabsf(c0 - g0) + fabsf(c1 - g1) + fabsf(c2 - g2);
                float np = sqrtf(c0 * c0 + c1 * c1 + c2 * c2);
                float ng = sqrtf(g0 * g0 + g1 * g1 + g2 * g2);
                float dt = c0 * g0 + c1 * g1 + c2 * g2;
                aCos += -dt / ((np + 1e-8f) * (ng + 1e-8f));
                aCnt += 1.f;
            }
        }
        __syncthreads();
    }

    float a = wsum(aL1), b = wsum(aCos), c = wsum(aCnt);
    int wid = tid >> 5, lid = tid & 31;
    if (lid == 0) { rb[wid] = a; rb[8 + wid] = b; rb[16 + wid] = c; }
    __syncthreads();

    __shared__ int s_last;
    if (tid == 0) {
        float x = 0.f, y = 0.f, z = 0.f;
        for (int i = 0; i < 8; i++) { x += rb[i]; y += rb[8 + i]; z += rb[16 + i]; }
        atomicAdd(&g_acc[2], (double)x);
        atomicAdd(&g_acc[3], (double)y);
        atomicAdd(&g_acc[4], (double)z);
        __threadfence();
        int ticket = atomicAdd(&g_done, 1);
        s_last = (ticket == gridDim.x - 1) ? 1 : 0;
    }
    __syncthreads();
    if (s_last && tid == 0) {
        double seg   = g_acc[0] / g_acc[1];
        double denom = g_acc[4] + 1e-8;
        double l1    = g_acc[2] / denom;
        double cs    = g_acc[3] / denom;
        out[0] = (float)(seg + l1 + cs);
        out[1] = (float)seg;
        out[2] = (float)l1;
        out[3] = (float)cs;
    }
}

// ---------------- launch ---------------------------------------------------------
extern "C" void kernel_launch(void* const* d_in, const int* in_sizes, int n_in,
                              void* d_out, int out_size)
{
    const float* feat     = (const float*)d_in[0];
    const float* coord    = (const float*)d_in[1];
    const int*   segment  = (const int*)d_in[2];
    const int*   instance = (const int*)d_in[3];
    const float* cent     = (const float*)d_in[4];
    const float* W1       = (const float*)d_in[5];
    // d_in[6] = b1 (cancels through BN)
    const float* gamma    = (const float*)d_in[7];
    const float* beta     = (const float*)d_in[8];
    const float* W2       = (const float*)d_in[9];
    const float* b2       = (const float*)d_in[10];
    const float* Wseg     = (const float*)d_in[11];
    const float* bseg     = (const float*)d_in[12];
    const float* cw       = (const float*)d_in[13];

    int N = in_sizes[0] / CC;
    if (N > NMAX) N = NMAX;
    int ntiles = (N + MT - 1) / MT;
    int nt3    = (N + 511) / 512;
    int grid1 = ntiles < 296 ? ntiles : 296;
    int grid3 = nt3 < 444 ? nt3 : 444;

    cudaFuncSetAttribute(pass1_kernel, cudaFuncAttributeMaxDynamicSharedMemorySize, SM1_BYTES);

    zero_kernel<<<1, 64>>>();
    pass1_kernel<<<grid1, 256, SM1_BYTES>>>(feat, segment, W1, Wseg, bseg, cw, N, ntiles);
    pass3_kernel<<<grid3, 256>>>(coord, instance, cent, b2, gamma, beta, W2,
                                 (float*)d_out, N, nt3);
}